// round 1
// baseline (speedup 1.0000x reference)
#include <cuda_runtime.h>
#include <cstddef>

// GeometricEdgeConv: B=8, N=16384, C=128, OUT=128, K=16
// out = leaky_relu( x @ Ws + [mean_k nbr_x, pos_i - mean_k nbr_pos, mean_k d2] @ We , 0.2 )
// Linearity of the edge MLP lets us average features BEFORE the matvec (16x fewer FLOPs).

#define BN      8
#define NPTS    16384        // points per batch (power of two: 2^14)
#define NSHIFT  14
#define CIN     128
#define COUT    128
#define KNB     16
#define P_TOTAL (BN * NPTS)  // 131072

#define TILE_M    64         // points per CTA
#define THREADS   256
#define KREAL     260        // 128 (x) + 128 (mean nbr_x) + 3 (mean rel) + 1 (mean d2)
#define KTOT      264        // padded to multiple of KT
#define AS_STRIDE 268        // smem row stride (floats); 4*268 % 32 == 16 -> conflict-free a-reads
#define KT        8
#define NTILES    (KTOT / KT) // 33

__global__ __launch_bounds__(THREADS, 2)
void gec_kernel(const float* __restrict__ x,
                const float* __restrict__ pos,
                const int*   __restrict__ idx,
                const float* __restrict__ w_self,
                const float* __restrict__ w_edge,
                float*       __restrict__ out)
{
    extern __shared__ float smem[];
    float* As = smem;                          // [TILE_M][AS_STRIDE] feature tile, row-major
    float* Bs = smem + TILE_M * AS_STRIDE;     // [KT][COUT] weight k-tile

    const int tid = threadIdx.x;
    const int g0  = blockIdx.x * TILE_M;       // first global point of this tile

    // ---------------- Phase 1a: stage this tile's own x rows into As[:, 0:128] ----------------
    {
        // 64 rows x 128 cols = 2048 float4, 8 per thread; one warp == one row (coalesced LDG)
        #pragma unroll
        for (int it = 0; it < 8; ++it) {
            int f4 = tid + it * THREADS;           // 0..2047
            int p  = f4 >> 5;                      // 32 float4 per row
            int c4 = f4 & 31;
            float4 v = *(reinterpret_cast<const float4*>(x + (size_t)(g0 + p) * CIN) + c4);
            float* dst = As + p * AS_STRIDE + c4 * 4;
            dst[0] = v.x; dst[1] = v.y; dst[2] = v.z; dst[3] = v.w;
        }
    }

    // ---------------- Phase 1b: gather + average neighbor features ----------------
    {
        const int p  = tid >> 2;                  // 0..63 local point
        const int q  = tid & 3;                   // 4 threads per point, 32 channels each
        const int gp = g0 + p;
        const int b  = gp >> NSHIFT;

        // neighbor indices (row is 64B-aligned)
        const int4* ip4 = reinterpret_cast<const int4*>(idx + (size_t)gp * KNB);
        int4 i0 = ip4[0], i1 = ip4[1], i2 = ip4[2], i3 = ip4[3];
        int nbr[KNB] = { i0.x, i0.y, i0.z, i0.w, i1.x, i1.y, i1.z, i1.w,
                         i2.x, i2.y, i2.z, i2.w, i3.x, i3.y, i3.z, i3.w };

        const float* xb    = x + (((size_t)b << NSHIFT)) * CIN;
        const int    cbase = q * 32;

        float4 acc[8];
        #pragma unroll
        for (int r = 0; r < 8; ++r) acc[r] = make_float4(0.f, 0.f, 0.f, 0.f);

        #pragma unroll 4
        for (int k = 0; k < KNB; ++k) {
            const float4* xr = reinterpret_cast<const float4*>(xb + (size_t)nbr[k] * CIN + cbase);
            #pragma unroll
            for (int r = 0; r < 8; ++r) {
                float4 v = xr[r];
                acc[r].x += v.x; acc[r].y += v.y; acc[r].z += v.z; acc[r].w += v.w;
            }
        }

        const float s = 1.0f / 16.0f;
        float* dst = As + p * AS_STRIDE + CIN + cbase;     // columns 128..255
        #pragma unroll
        for (int r = 0; r < 8; ++r) {
            dst[r * 4 + 0] = acc[r].x * s;
            dst[r * 4 + 1] = acc[r].y * s;
            dst[r * 4 + 2] = acc[r].z * s;
            dst[r * 4 + 3] = acc[r].w * s;
        }

        if (q == 0) {
            // geometric features: mean relative position + mean squared distance
            const float* pp = pos + (size_t)gp * 3;
            float px = pp[0], py = pp[1], pz = pp[2];
            const float* posb = pos + (((size_t)b << NSHIFT)) * 3;
            float sx = 0.f, sy = 0.f, sz = 0.f, sd = 0.f;
            #pragma unroll
            for (int k = 0; k < KNB; ++k) {
                const float* nb = posb + (size_t)nbr[k] * 3;
                float rx = px - nb[0], ry = py - nb[1], rz = pz - nb[2];
                sx += rx; sy += ry; sz += rz;
                sd += rx * rx + ry * ry + rz * rz;
            }
            float* d2 = As + p * AS_STRIDE + 256;
            d2[0] = sx * s; d2[1] = sy * s; d2[2] = sz * s; d2[3] = sd * s;  // k = 256..259
            d2[4] = 0.f; d2[5] = 0.f; d2[6] = 0.f; d2[7] = 0.f;             // k = 260..263 pad
        }
    }

    // ---------------- Phase 2: register-tiled GEMM  C[64][128] += As[64][264] * W[264][128] ----
    const int tx = tid & 15;    // 8 output cols each: o = tx*8 .. tx*8+7
    const int ty = tid >> 4;    // 4 points each:      p = ty*4 .. ty*4+3

    float accb[4][8];
    #pragma unroll
    for (int i = 0; i < 4; ++i)
        #pragma unroll
        for (int j = 0; j < 8; ++j) accb[i][j] = 0.f;

    // W k-tile loader: combined [264][128] row k -> w_self (k<128), w_edge (128<=k<260), else 0
    const int lk = tid >> 5;          // row within tile (8 rows, 32 threads each)
    const int lo = (tid & 31) * 4;    // 4 consecutive output cols

    float4 pre;
    {
        int k = 0 * KT + lk;
        pre = *reinterpret_cast<const float4*>(w_self + (size_t)k * COUT + lo);
    }

    for (int kt = 0; kt < NTILES; ++kt) {
        __syncthreads();                                   // Bs free (also fences Phase 1)
        *reinterpret_cast<float4*>(Bs + lk * COUT + lo) = pre;
        __syncthreads();                                   // Bs ready

        if (kt + 1 < NTILES) {                             // prefetch next W tile
            int k = (kt + 1) * KT + lk;
            if (k < CIN)
                pre = *reinterpret_cast<const float4*>(w_self + (size_t)k * COUT + lo);
            else if (k < KREAL)
                pre = *reinterpret_cast<const float4*>(w_edge + (size_t)(k - CIN) * COUT + lo);
            else
                pre = make_float4(0.f, 0.f, 0.f, 0.f);
        }

        #pragma unroll
        for (int kk = 0; kk < KT; ++kk) {
            float a[4];
            #pragma unroll
            for (int i = 0; i < 4; ++i)
                a[i] = As[(ty * 4 + i) * AS_STRIDE + kt * KT + kk];
            float4 b0 = *reinterpret_cast<float4*>(Bs + kk * COUT + tx * 8);
            float4 b1 = *reinterpret_cast<float4*>(Bs + kk * COUT + tx * 8 + 4);
            #pragma unroll
            for (int i = 0; i < 4; ++i) {
                accb[i][0] = fmaf(a[i], b0.x, accb[i][0]);
                accb[i][1] = fmaf(a[i], b0.y, accb[i][1]);
                accb[i][2] = fmaf(a[i], b0.z, accb[i][2]);
                accb[i][3] = fmaf(a[i], b0.w, accb[i][3]);
                accb[i][4] = fmaf(a[i], b1.x, accb[i][4]);
                accb[i][5] = fmaf(a[i], b1.y, accb[i][5]);
                accb[i][6] = fmaf(a[i], b1.z, accb[i][6]);
                accb[i][7] = fmaf(a[i], b1.w, accb[i][7]);
            }
        }
    }

    // ---------------- Epilogue: leaky_relu(0.2) + coalesced float4 stores ----------------
    #pragma unroll
    for (int i = 0; i < 4; ++i) {
        int p = ty * 4 + i;
        float* op = out + (size_t)(g0 + p) * COUT + tx * 8;
        float4 o0, o1;
        float v;
        v = accb[i][0]; o0.x = v > 0.f ? v : 0.2f * v;
        v = accb[i][1]; o0.y = v > 0.f ? v : 0.2f * v;
        v = accb[i][2]; o0.z = v > 0.f ? v : 0.2f * v;
        v = accb[i][3]; o0.w = v > 0.f ? v : 0.2f * v;
        v = accb[i][4]; o1.x = v > 0.f ? v : 0.2f * v;
        v = accb[i][5]; o1.y = v > 0.f ? v : 0.2f * v;
        v = accb[i][6]; o1.z = v > 0.f ? v : 0.2f * v;
        v = accb[i][7]; o1.w = v > 0.f ? v : 0.2f * v;
        *reinterpret_cast<float4*>(op)     = o0;
        *reinterpret_cast<float4*>(op + 4) = o1;
    }
}

extern "C" void kernel_launch(void* const* d_in, const int* in_sizes, int n_in,
                              void* d_out, int out_size)
{
    const float* x      = (const float*)d_in[0];
    const float* pos    = (const float*)d_in[1];
    const int*   idx    = (const int*)  d_in[2];
    const float* w_self = (const float*)d_in[3];
    const float* w_edge = (const float*)d_in[4];
    float* out = (float*)d_out;

    size_t smem_bytes = (size_t)(TILE_M * AS_STRIDE + KT * COUT) * sizeof(float); // 72704 B
    cudaFuncSetAttribute(gec_kernel, cudaFuncAttributeMaxDynamicSharedMemorySize,
                         (int)smem_bytes);

    gec_kernel<<<P_TOTAL / TILE_M, THREADS, smem_bytes>>>(x, pos, idx, w_self, w_edge, out);
}

// round 6
// speedup vs baseline: 1.4599x; 1.4599x over previous
#include <cuda_runtime.h>
#include <cstddef>

// GeometricEdgeConv: B=8, N=16384, C=128, OUT=128, K=16
// out = leaky_relu( x @ Ws + [mean_k nbr_x, pos_i - mean_k nbr_pos, mean_k d2] @ We , 0.2 )
// Linearity of the edge MLP: average features BEFORE the matvec (16x fewer FLOPs).
// GEMM inner loop uses sm_103a packed fma.rn.f32x2 (2 fp32 FMA lanes / instr).

#define BN      8
#define NPTS    16384
#define NSHIFT  14
#define CIN     128
#define COUT    128
#define KNB     16
#define P_TOTAL (BN * NPTS)   // 131072

#define TILE_M    64          // points per CTA
#define THREADS   256
#define KREAL     260         // 128 (x) + 128 (mean nbr_x) + 3 (mean rel) + 1 (mean d2)
#define KTOT      264         // padded to multiple of KT
#define AS_STRIDE 268         // smem row stride (floats), 16B-aligned rows
#define KT        8
#define NTILES    (KTOT / KT) // 33

// ---- packed f32x2 helpers (sm_103a) ----
__device__ __forceinline__ void ffma2(unsigned long long& d,
                                      unsigned long long a,
                                      unsigned long long b)
{
    // d.lo += a.lo*b.lo ; d.hi += a.hi*b.hi
    asm("fma.rn.f32x2 %0, %1, %2, %0;" : "+l"(d) : "l"(a), "l"(b));
}
__device__ __forceinline__ unsigned long long bcast2(float a)
{
    unsigned long long r;
    asm("mov.b64 %0, {%1, %1};" : "=l"(r) : "f"(a));
    return r;
}
__device__ __forceinline__ void unpack2(float& lo, float& hi, unsigned long long v)
{
    asm("mov.b64 {%0, %1}, %2;" : "=f"(lo), "=f"(hi) : "l"(v));
}

__global__ __launch_bounds__(THREADS, 2)
void gec_kernel(const float* __restrict__ x,
                const float* __restrict__ pos,
                const int*   __restrict__ idx,
                const float* __restrict__ w_self,
                const float* __restrict__ w_edge,
                float*       __restrict__ out)
{
    extern __shared__ float smem[];
    float* As = smem;                          // [TILE_M][AS_STRIDE]
    float* Bs = smem + TILE_M * AS_STRIDE;     // [KT][COUT]

    const int tid  = threadIdx.x;
    const int lane = tid & 31;
    const int warp = tid >> 5;                 // 0..7
    const int g0   = blockIdx.x * TILE_M;

    // ---------------- Phase 1a: stage own x rows into As[:, 0:128] (coalesced) ----------------
    #pragma unroll
    for (int it = 0; it < 8; ++it) {
        int f4 = tid + it * THREADS;           // 0..2047 ; 32 float4 per row
        int p  = f4 >> 5;
        int c4 = f4 & 31;
        float4 v = *(reinterpret_cast<const float4*>(x + (size_t)(g0 + p) * CIN) + c4);
        float* dst = As + p * AS_STRIDE + c4 * 4;
        dst[0] = v.x; dst[1] = v.y; dst[2] = v.z; dst[3] = v.w;
    }

    // ---------------- Phase 1b: warp-per-point coalesced gather ----------------
    // Warp w handles points p = w*8 .. w*8+7. For each point:
    //   lanes 0-15 hold the 16 neighbor indices; each neighbor's 512B feature row
    //   is loaded by the FULL warp (lane = 16B chunk) -> 4 lines per LDG.128, coalesced.
    {
        const int l16 = lane & 15;
        #pragma unroll
        for (int i = 0; i < 8; ++i) {
            const int p  = warp * 8 + i;
            const int gp = g0 + p;
            const int b  = gp >> NSHIFT;
            const float* xb   = x   + (((size_t)b << NSHIFT)) * CIN;
            const float* posb = pos + (((size_t)b << NSHIFT)) * 3;

            int my = idx[(size_t)gp * KNB + l16];      // lanes 16-31 duplicate lanes 0-15

            // feature gather: 16 coalesced 512B row loads
            float4 acc = make_float4(0.f, 0.f, 0.f, 0.f);
            #pragma unroll
            for (int k = 0; k < KNB; ++k) {
                int n = __shfl_sync(0xffffffffu, my, k);
                float4 v = *(reinterpret_cast<const float4*>(xb + (size_t)n * CIN) + lane);
                acc.x += v.x; acc.y += v.y; acc.z += v.z; acc.w += v.w;
            }

            // geometric features: lane k (<16) handles neighbor k
            float px = pos[(size_t)gp * 3 + 0];
            float py = pos[(size_t)gp * 3 + 1];
            float pz = pos[(size_t)gp * 3 + 2];
            float rx = 0.f, ry = 0.f, rz = 0.f, rd = 0.f;
            if (lane < KNB) {
                const float* nb = posb + (size_t)my * 3;
                float ax = px - nb[0], ay = py - nb[1], az = pz - nb[2];
                rx = ax; ry = ay; rz = az;
                rd = ax * ax + ay * ay + az * az;
            }
            #pragma unroll
            for (int s = 8; s >= 1; s >>= 1) {
                rx += __shfl_xor_sync(0xffffffffu, rx, s, 16);
                ry += __shfl_xor_sync(0xffffffffu, ry, s, 16);
                rz += __shfl_xor_sync(0xffffffffu, rz, s, 16);
                rd += __shfl_xor_sync(0xffffffffu, rd, s, 16);
            }

            const float sc = 1.0f / 16.0f;
            float* dst = As + p * AS_STRIDE + CIN + lane * 4;   // cols 128..255, 16B-aligned
            float4 o = make_float4(acc.x * sc, acc.y * sc, acc.z * sc, acc.w * sc);
            *reinterpret_cast<float4*>(dst) = o;

            if (lane == 0) {
                float* gq = As + p * AS_STRIDE + 256;
                gq[0] = rx * sc; gq[1] = ry * sc; gq[2] = rz * sc; gq[3] = rd * sc;
                gq[4] = 0.f; gq[5] = 0.f; gq[6] = 0.f; gq[7] = 0.f;   // pad k=260..263
            }
        }
    }

    // ---------------- Phase 2: register-tiled GEMM  C[64][128] = As[64][264] * W[264][128] ----
    const int tx = tid & 15;    // 8 output cols:  o = tx*8 .. tx*8+7
    const int ty = tid >> 4;    // 4 points:       p = ty*4 .. ty*4+3

    // packed accumulators: acc[i][j] = (out[2j], out[2j+1]) for point ty*4+i
    unsigned long long accp[4][4];
    #pragma unroll
    for (int i = 0; i < 4; ++i)
        #pragma unroll
        for (int j = 0; j < 4; ++j) accp[i][j] = 0ull;

    // W k-tile loader: combined [264][128]: w_self (k<128), w_edge (128<=k<260), else 0
    const int lk = tid >> 5;          // tile row (8 rows x 32 threads)
    const int lo = (tid & 31) * 4;    // 4 output cols

    float4 pre = *reinterpret_cast<const float4*>(w_self + (size_t)lk * COUT + lo);

    for (int kt = 0; kt < NTILES; ++kt) {
        __syncthreads();                                   // Bs free (first iter: fences Phase 1)
        *reinterpret_cast<float4*>(Bs + lk * COUT + lo) = pre;
        __syncthreads();                                   // Bs ready

        if (kt + 1 < NTILES) {
            int k = (kt + 1) * KT + lk;
            if (k < CIN)
                pre = *reinterpret_cast<const float4*>(w_self + (size_t)k * COUT + lo);
            else if (k < KREAL)
                pre = *reinterpret_cast<const float4*>(w_edge + (size_t)(k - CIN) * COUT + lo);
            else
                pre = make_float4(0.f, 0.f, 0.f, 0.f);
        }

        // vectorized A loads along k: 2 x LDS.128 per point (broadcast across tx lanes)
        float4 av0[4], av1[4];
        #pragma unroll
        for (int i = 0; i < 4; ++i) {
            const float* ar = As + (ty * 4 + i) * AS_STRIDE + kt * KT;
            av0[i] = *reinterpret_cast<const float4*>(ar);
            av1[i] = *reinterpret_cast<const float4*>(ar + 4);
        }

        #pragma unroll
        for (int kk = 0; kk < KT; ++kk) {
            // B row, pre-packed as f32x2 pairs via 64-bit shared loads
            const ulonglong2* brow =
                reinterpret_cast<const ulonglong2*>(Bs + kk * COUT + tx * 8);
            ulonglong2 bp0 = brow[0];   // cols 0-3  -> two packed pairs
            ulonglong2 bp1 = brow[1];   // cols 4-7

            #pragma unroll
            for (int i = 0; i < 4; ++i) {
                float a;
                switch (kk) {
                    case 0: a = av0[i].x; break;
                    case 1: a = av0[i].y; break;
                    case 2: a = av0[i].z; break;
                    case 3: a = av0[i].w; break;
                    case 4: a = av1[i].x; break;
                    case 5: a = av1[i].y; break;
                    case 6: a = av1[i].z; break;
                    default: a = av1[i].w; break;
                }
                unsigned long long aa = bcast2(a);
                ffma2(accp[i][0], aa, bp0.x);
                ffma2(accp[i][1], aa, bp0.y);
                ffma2(accp[i][2], aa, bp1.x);
                ffma2(accp[i][3], aa, bp1.y);
            }
        }
    }

    // ---------------- Epilogue: unpack + leaky_relu(0.2) + coalesced float4 stores ----------------
    #pragma unroll
    for (int i = 0; i < 4; ++i) {
        int p = ty * 4 + i;
        float* op = out + (size_t)(g0 + p) * COUT + tx * 8;
        float r[8];
        unpack2(r[0], r[1], accp[i][0]);
        unpack2(r[2], r[3], accp[i][1]);
        unpack2(r[4], r[5], accp[i][2]);
        unpack2(r[6], r[7], accp[i][3]);
        float4 o0, o1;
        float v;
        v = r[0]; o0.x = v > 0.f ? v : 0.2f * v;
        v = r[1]; o0.y = v > 0.f ? v : 0.2f * v;
        v = r[2]; o0.z = v > 0.f ? v : 0.2f * v;
        v = r[3]; o0.w = v > 0.f ? v : 0.2f * v;
        v = r[4]; o1.x = v > 0.f ? v : 0.2f * v;
        v = r[5]; o1.y = v > 0.f ? v : 0.2f * v;
        v = r[6]; o1.z = v > 0.f ? v : 0.2f * v;
        v = r[7]; o1.w = v > 0.f ? v : 0.2f * v;
        *reinterpret_cast<float4*>(op)     = o0;
        *reinterpret_cast<float4*>(op + 4) = o1;
    }
}

extern "C" void kernel_launch(void* const* d_in, const int* in_sizes, int n_in,
                              void* d_out, int out_size)
{
    const float* x      = (const float*)d_in[0];
    const float* pos    = (const float*)d_in[1];
    const int*   idx    = (const int*)  d_in[2];
    const float* w_self = (const float*)d_in[3];
    const float* w_edge = (const float*)d_in[4];
    float* out = (float*)d_out;

    size_t smem_bytes = (size_t)(TILE_M * AS_STRIDE + KT * COUT) * sizeof(float); // 72704 B
    cudaFuncSetAttribute(gec_kernel, cudaFuncAttributeMaxDynamicSharedMemorySize,
                         (int)smem_bytes);

    gec_kernel<<<P_TOTAL / TILE_M, THREADS, smem_bytes>>>(x, pos, idx, w_self, w_edge, out);
}